// round 3
// baseline (speedup 1.0000x reference)
#include <cuda_runtime.h>
#include <math.h>

#define NUM_FEATURES 10
#define EMBED 256
#define MAXLEN 366
#define PE_ROWS (MAXLEN + 1)
#define OUT_DIM (2 * EMBED)
#define MAX_TOK_PER_BLOCK 224   // ceil(131072/592)=222, rounded up

// Positional-encoding table: row 0 zeros, rows 1..366 sin/cos for pos 0..365.
__device__ float g_pe[PE_ROWS * EMBED];

// ---------------------------------------------------------------------------
// Fill PE table (single precision MUFU path, ~5e-5 abs err vs fp32 numpy).
// ---------------------------------------------------------------------------
__global__ void fill_pe_kernel() {
    int idx = blockIdx.x * blockDim.x + threadIdx.x;
    const int pairs = EMBED / 2;
    if (idx >= PE_ROWS * pairs) return;
    int row = idx / pairs;
    int i   = idx - row * pairs;
    float s = 0.0f, c = 0.0f;
    if (row > 0) {
        const float k = -(logf(10000.0f) / (float)EMBED);
        float div = expf((float)(2 * i) * k);
        sincosf((float)(row - 1) * div, &s, &c);
    }
    g_pe[row * EMBED + 2 * i]     = s;
    g_pe[row * EMBED + 2 * i + 1] = c;
}

// ---------------------------------------------------------------------------
// Packed f32x2 helpers (sm_103a dual-issue FMA; PTX-only, ptxas won't fuse).
// ---------------------------------------------------------------------------
__device__ __forceinline__ unsigned long long pack2(float a, float b) {
    unsigned long long r;
    asm("mov.b64 %0, {%1, %2};" : "=l"(r) : "f"(a), "f"(b));
    return r;
}
__device__ __forceinline__ unsigned long long fma2(unsigned long long a,
                                                   unsigned long long b,
                                                   unsigned long long c) {
    unsigned long long d;
    asm("fma.rn.f32x2 %0, %1, %2, %3;" : "=l"(d) : "l"(a), "l"(b), "l"(c));
    return d;
}

// ---------------------------------------------------------------------------
// Main kernel, role-split:
//   warps 0-3 (tid 0..127): obs half. e_lane=tid&63 owns 4 channels; 2 token
//     lanes. Weights pre-packed into f32x2 pairs in regs; x read from smem as
//     pre-duplicated float2 broadcasts (1 LDS.64 -> feeds 2 packed FMAs).
//   warps 4-7 (tid 128..255): PE half. Pure gather+copy, unrolled 4 deep so
//     4 independent L2 gathers are in flight per thread.
// Both halves write float4 (STG.128) coalesced streaming stores.
// ---------------------------------------------------------------------------
__global__ __launch_bounds__(256, 4)
void bert_embed_kernel(const float* __restrict__ x,     // [ntok, 10]
                       const int*   __restrict__ doy,   // [ntok]
                       const float* __restrict__ W,     // [256, 10]
                       const float* __restrict__ bias_g,// [256]
                       float*       __restrict__ out,   // [ntok, 512]
                       int ntok) {
    __shared__ float2 sx2[MAX_TOK_PER_BLOCK * NUM_FEATURES];  // duplicated x
    __shared__ int    sdoy[MAX_TOK_PER_BLOCK];

    const int per = (ntok + gridDim.x - 1) / gridDim.x;
    const int t0  = blockIdx.x * per;
    const int cnt = min(per, ntok - t0);
    if (cnt <= 0) return;

    // Stage x (duplicated into both float2 lanes) + doy. Coalesced LDG.
    for (int i = threadIdx.x; i < cnt * NUM_FEATURES; i += blockDim.x) {
        float v = __ldg(x + (size_t)t0 * NUM_FEATURES + i);
        sx2[i] = make_float2(v, v);
    }
    for (int i = threadIdx.x; i < cnt; i += blockDim.x)
        sdoy[i] = __ldg(doy + t0 + i);

    const int tid = threadIdx.x;

    if (tid < 128) {
        // ---------------- obs role ----------------
        const int e_lane = tid & 63;
        const int t_lane = tid >> 6;          // 0 or 1
        const int e0 = e_lane * 4;

        // Pack this thread's W[4][10] slice as f32x2 pairs + packed bias.
        unsigned long long wp01[NUM_FEATURES], wp23[NUM_FEATURES];
#pragma unroll
        for (int f = 0; f < NUM_FEATURES; f++) {
            wp01[f] = pack2(__ldg(W + (e0 + 0) * NUM_FEATURES + f),
                            __ldg(W + (e0 + 1) * NUM_FEATURES + f));
            wp23[f] = pack2(__ldg(W + (e0 + 2) * NUM_FEATURES + f),
                            __ldg(W + (e0 + 3) * NUM_FEATURES + f));
        }
        const unsigned long long b01 = pack2(__ldg(bias_g + e0),     __ldg(bias_g + e0 + 1));
        const unsigned long long b23 = pack2(__ldg(bias_g + e0 + 2), __ldg(bias_g + e0 + 3));

        __syncthreads();

#pragma unroll 2
        for (int tt = t_lane; tt < cnt; tt += 2) {
            const unsigned long long* xp =
                reinterpret_cast<const unsigned long long*>(sx2 + tt * NUM_FEATURES);
            unsigned long long a01 = b01, a23 = b23;
#pragma unroll
            for (int f = 0; f < NUM_FEATURES; f++) {
                unsigned long long xx = xp[f];     // LDS.64 broadcast {v,v}
                a01 = fma2(xx, wp01[f], a01);
                a23 = fma2(xx, wp23[f], a23);
            }
            ulonglong2 res; res.x = a01; res.y = a23;
            __stcs(reinterpret_cast<ulonglong2*>(out + (size_t)(t0 + tt) * OUT_DIM + e0), res);
        }
    } else {
        // ---------------- PE role ----------------
        const int tid2 = tid - 128;
        const int e_lane = tid2 & 63;
        const int t_lane = tid2 >> 6;         // 0 or 1
        const int c0 = e_lane * 4;            // column within PE half

        __syncthreads();

        int tt = t_lane;
        for (; tt + 6 < cnt; tt += 8) {
            int d0 = sdoy[tt], d1 = sdoy[tt + 2], d2 = sdoy[tt + 4], d3 = sdoy[tt + 6];
            float4 p0 = *reinterpret_cast<const float4*>(&g_pe[d0 * EMBED + c0]);
            float4 p1 = *reinterpret_cast<const float4*>(&g_pe[d1 * EMBED + c0]);
            float4 p2 = *reinterpret_cast<const float4*>(&g_pe[d2 * EMBED + c0]);
            float4 p3 = *reinterpret_cast<const float4*>(&g_pe[d3 * EMBED + c0]);
            __stcs(reinterpret_cast<float4*>(out + (size_t)(t0 + tt)     * OUT_DIM + EMBED + c0), p0);
            __stcs(reinterpret_cast<float4*>(out + (size_t)(t0 + tt + 2) * OUT_DIM + EMBED + c0), p1);
            __stcs(reinterpret_cast<float4*>(out + (size_t)(t0 + tt + 4) * OUT_DIM + EMBED + c0), p2);
            __stcs(reinterpret_cast<float4*>(out + (size_t)(t0 + tt + 6) * OUT_DIM + EMBED + c0), p3);
        }
        for (; tt < cnt; tt += 2) {
            int d = sdoy[tt];
            float4 p = *reinterpret_cast<const float4*>(&g_pe[d * EMBED + c0]);
            __stcs(reinterpret_cast<float4*>(out + (size_t)(t0 + tt) * OUT_DIM + EMBED + c0), p);
        }
    }
}

extern "C" void kernel_launch(void* const* d_in, const int* in_sizes, int n_in,
                              void* d_out, int out_size) {
    const float* x    = (const float*)d_in[0];   // input_sequence [256,512,10]
    const int*   doy  = (const int*)  d_in[1];   // doy_sequence   [256,512]
    const float* W    = (const float*)d_in[2];   // [256,10]
    const float* b    = (const float*)d_in[3];   // [256]
    float*       out  = (float*)d_out;           // [256,512,512]

    const int ntok = in_sizes[1];                // 131072 tokens

    const int pe_threads = PE_ROWS * (EMBED / 2);
    fill_pe_kernel<<<(pe_threads + 255) / 256, 256>>>();

    bert_embed_kernel<<<592, 256>>>(x, doy, W, b, out, ntok);
}

// round 4
// speedup vs baseline: 1.0500x; 1.0500x over previous
#include <cuda_runtime.h>
#include <math.h>

#define NUM_FEATURES 10
#define EMBED 256
#define MAXLEN 366
#define PE_ROWS (MAXLEN + 1)
#define OUT_DIM (2 * EMBED)
#define GRID 740                 // 148 SMs x 5 resident blocks, single wave
#define MAX_TOK_PER_BLOCK 180    // ceil(131072/740)=178, rounded up

// Positional-encoding table: row 0 zeros, rows 1..366 sin/cos for pos 0..365.
__device__ float g_pe[PE_ROWS * EMBED];

// ---------------------------------------------------------------------------
// Fill PE table (single precision MUFU path, ~5e-5 abs err vs fp32 numpy).
// ---------------------------------------------------------------------------
__global__ void fill_pe_kernel() {
    int idx = blockIdx.x * blockDim.x + threadIdx.x;
    const int pairs = EMBED / 2;
    if (idx >= PE_ROWS * pairs) return;
    int row = idx / pairs;
    int i   = idx - row * pairs;
    float s = 0.0f, c = 0.0f;
    if (row > 0) {
        const float k = -(logf(10000.0f) / (float)EMBED);
        float div = expf((float)(2 * i) * k);
        sincosf((float)(row - 1) * div, &s, &c);
    }
    g_pe[row * EMBED + 2 * i]     = s;
    g_pe[row * EMBED + 2 * i + 1] = c;
}

// ---------------------------------------------------------------------------
// Packed f32x2 helpers (sm_103a dual FMA; PTX-only, ptxas won't auto-fuse).
// ---------------------------------------------------------------------------
__device__ __forceinline__ unsigned long long pack2(float a, float b) {
    unsigned long long r;
    asm("mov.b64 %0, {%1, %2};" : "=l"(r) : "f"(a), "f"(b));
    return r;
}
__device__ __forceinline__ unsigned long long fma2(unsigned long long a,
                                                   unsigned long long b,
                                                   unsigned long long c) {
    unsigned long long d;
    asm("fma.rn.f32x2 %0, %1, %2, %3;" : "=l"(d) : "l"(a), "l"(b), "l"(c));
    return d;
}
__device__ __forceinline__ float2 unpack2(unsigned long long v) {
    float lo, hi;
    asm("mov.b64 {%0, %1}, %2;" : "=f"(lo), "=f"(hi) : "l"(v));
    return make_float2(lo, hi);
}

// ---------------------------------------------------------------------------
// Main kernel: uniform roles, software-pipelined PE gather.
// e_lane = tid & 127 owns 2 obs channels (f32x2 regs) and the matching 2 PE
// channels; t_lane = tid >> 7 gives 2 token lanes. The PE gather for token
// t+2 is issued BEFORE token t's FMA chain, so its L1/L2 latency is hidden
// behind compute and the previous stores.
// ---------------------------------------------------------------------------
__global__ __launch_bounds__(256, 5)
void bert_embed_kernel(const float* __restrict__ x,     // [ntok, 10]
                       const int*   __restrict__ doy,   // [ntok]
                       const float* __restrict__ W,     // [256, 10]
                       const float* __restrict__ bias_g,// [256]
                       float*       __restrict__ out,   // [ntok, 512]
                       int ntok) {
    __shared__ float2 sx2[MAX_TOK_PER_BLOCK * NUM_FEATURES];  // x duplicated {v,v}
    __shared__ int    sdoy[MAX_TOK_PER_BLOCK];

    const int per = (ntok + GRID - 1) / GRID;      // 178
    const int t0  = blockIdx.x * per;
    const int cnt = min(per, ntok - t0);
    if (cnt <= 0) return;

    // Stage x (pre-duplicated for packed FMA) + doy. Coalesced LDG.
    for (int i = threadIdx.x; i < cnt * NUM_FEATURES; i += blockDim.x) {
        float v = __ldg(x + (size_t)t0 * NUM_FEATURES + i);
        sx2[i] = make_float2(v, v);
    }
    for (int i = threadIdx.x; i < cnt; i += blockDim.x)
        sdoy[i] = __ldg(doy + t0 + i);

    const int e_lane = threadIdx.x & 127;
    const int t_lane = threadIdx.x >> 7;           // 0 or 1
    const int e0 = e_lane * 2;

    // This thread's packed W[2][10] slice + packed bias (20+2 regs).
    unsigned long long wp[NUM_FEATURES];
#pragma unroll
    for (int f = 0; f < NUM_FEATURES; f++)
        wp[f] = pack2(__ldg(W + (e0 + 0) * NUM_FEATURES + f),
                      __ldg(W + (e0 + 1) * NUM_FEATURES + f));
    const unsigned long long b01 = pack2(__ldg(bias_g + e0), __ldg(bias_g + e0 + 1));

    __syncthreads();

    int tt = t_lane;
    // Prologue: gather PE for the first token.
    float2 pev = make_float2(0.f, 0.f);
    if (tt < cnt)
        pev = *reinterpret_cast<const float2*>(&g_pe[sdoy[tt] * EMBED + e0]);

    for (; tt < cnt; tt += 2) {
        // Prefetch next iteration's PE gather (row 0 = zeros is a safe dummy).
        const int tn = tt + 2;
        const int dn = (tn < cnt) ? sdoy[tn] : 0;
        const float2 pev_next =
            *reinterpret_cast<const float2*>(&g_pe[dn * EMBED + e0]);

        // Obs: 10 packed FMAs fed by smem broadcast LDS.64.
        const unsigned long long* xp =
            reinterpret_cast<const unsigned long long*>(sx2 + tt * NUM_FEATURES);
        unsigned long long a = b01;
#pragma unroll
        for (int f = 0; f < NUM_FEATURES; f++)
            a = fma2(xp[f], wp[f], a);

        float* op = out + (size_t)(t0 + tt) * OUT_DIM;
        __stcs(reinterpret_cast<float2*>(op + e0),         unpack2(a));
        __stcs(reinterpret_cast<float2*>(op + EMBED + e0), pev);

        pev = pev_next;
    }
}

extern "C" void kernel_launch(void* const* d_in, const int* in_sizes, int n_in,
                              void* d_out, int out_size) {
    const float* x    = (const float*)d_in[0];   // input_sequence [256,512,10]
    const int*   doy  = (const int*)  d_in[1];   // doy_sequence   [256,512]
    const float* W    = (const float*)d_in[2];   // [256,10]
    const float* b    = (const float*)d_in[3];   // [256]
    float*       out  = (float*)d_out;           // [256,512,512]

    const int ntok = in_sizes[1];                // 131072 tokens

    const int pe_threads = PE_ROWS * (EMBED / 2);
    fill_pe_kernel<<<(pe_threads + 255) / 256, 256>>>();

    bert_embed_kernel<<<GRID, 256>>>(x, doy, W, b, out, ntok);
}